// round 14
// baseline (speedup 1.0000x reference)
#include <cuda_runtime.h>
#include <math.h>

#define FULL 0xffffffffu

constexpr int B = 128, J = 32, I = 1152, N = 16;
constexpr int TI = 24;             // i per tile: 8 warps x 3 i
constexpr int ROW = TI * N + 4;    // 388: lane stride 4 words mod 32 -> conflict-free LDS.128
constexpr int NCHB = 2;            // blocks per batch
constexpr int IPB = I / NCHB;      // 576
constexpr int TPT = IPB / TI;      // 24 tiles
constexpr int TPB = 256, WARPS = 8;
constexpr int KTH = 8;             // int(0.3*32)-1
constexpr int BUF = J * ROW;       // 12416 floats per buffer
constexpr int REDSTRIDE = 544;     // 32*17
constexpr int F4PJ = TI * N / 4;   // 96 float4 per j-row
constexpr int SMEM_FLOATS = 2 * BUF + 512 + 8 + IPB;  // 25928 floats = 103.7 KB

__device__ float g_spart[3][NCHB][B][J * N];
__device__ float g_entp[2][B * NCHB];
__device__ int g_sync[B][3];
__device__ int g_done;

__device__ __forceinline__ float warp_sum(float x) {
#pragma unroll
  for (int m = 16; m; m >>= 1) x += __shfl_xor_sync(FULL, x, m);
  return x;
}
__device__ __forceinline__ float grp16_sum(float x) {
#pragma unroll
  for (int m = 8; m; m >>= 1) x += __shfl_xor_sync(FULL, x, m);
  return x;
}

// combine two chunk partials (via L2) -> s; bias + reset + squash -> v (smem)
__device__ __forceinline__ void combine_v(const float* __restrict__ p0,
                                          const float* __restrict__ p1,
                                          const float* __restrict__ bias,
                                          float* vout, int tid) {
#pragma unroll
  for (int r = 0; r < 2; ++r) {
    int e = tid + r * TPB;  // e = j*16+n, 16-groups warp-aligned
    float s = __ldcg(p0 + e) + __ldcg(p1 + e);
    float ssum = grp16_sum(s);
    float sb = (ssum == 0.f) ? 0.f : s + bias[e];
    float sq = grp16_sum(sb * sb);
    vout[e] = (sq > 0.f) ? sb * (sq / (1.f + sq)) * rsqrtf(sq) : 0.f;
  }
}

__global__ void __launch_bounds__(TPB, 2) routing_kernel(const float* __restrict__ u,
                                                         const float* __restrict__ bias,
                                                         float* __restrict__ out,
                                                         int has_stats) {
  extern __shared__ float smem[];
  float* buf0 = smem;
  float* buf1 = smem + BUF;
  float* vs = smem + 2 * BUF;  // 512
  float* entw = vs + 512;      // 8
  unsigned* maskb = (unsigned*)(entw + 8);  // IPB words
  float* red = smem;           // ALIAS buf0: used only with cp.async pipeline drained

  const int b = blockIdx.y, g = blockIdx.x;
  const int tid = threadIdx.x, w = tid >> 5, lane = tid & 31;
  const int ibase = g * IPB;

  auto issue = [&](int pt, int sel) {
    float* buf = sel ? buf1 : buf0;
#pragma unroll
    for (int k = 0; k < 12; ++k) {
      int f = tid + k * TPB;            // 3072 x 16B
      int j = f / F4PJ, o = f - j * F4PJ;
      const float* gp = u + (((size_t)b * J + j) * I + (ibase + pt * TI)) * N + o * 4;
      unsigned sa = (unsigned)__cvta_generic_to_shared(buf + j * ROW + o * 4);
      asm volatile("cp.async.cg.shared.global [%0], [%1], 16;\n" ::"r"(sa), "l"(gp));
    }
    asm volatile("cp.async.commit_group;\n");
  };

  auto signal_wait = [&](int ph) {
    __threadfence();
    __syncthreads();
    if (tid == 0) {
      atomicAdd(&g_sync[b][ph], 1);
      while (atomicAdd(&g_sync[b][ph], 0) < 2) {}
      __threadfence();
    }
    __syncthreads();
  };

  // ================= PASS 0: direct streaming sum, c = 1/32 =================
  {
    const int half = tid >> 7, t2 = tid & 127, j0 = t2 >> 2, n4 = t2 & 3;
    const float4* p =
        (const float4*)(u + (((size_t)b * J + j0) * I + ibase + half * (IPB / 2)) * N) + n4;
    float4 a = make_float4(0.f, 0.f, 0.f, 0.f);
#pragma unroll 8
    for (int i = 0; i < IPB / 2; ++i) {
      float4 x = p[i * 4];
      a.x += x.x; a.y += x.y; a.z += x.z; a.w += x.w;
    }
    float4* rf = (float4*)red;  // aliases buf0 (no cp.async outstanding yet)
    rf[tid] = a;
    __syncthreads();
    if (tid < 128) {
      float4 a0 = rf[tid], a1 = rf[tid + 128];
      float4 s = make_float4((a0.x + a1.x) * (1.f / 32.f), (a0.y + a1.y) * (1.f / 32.f),
                             (a0.z + a1.z) * (1.f / 32.f), (a0.w + a1.w) * (1.f / 32.f));
      __stcg((float4*)(g_spart[0][g][b] + j0 * 16 + n4 * 4), s);
    }
    __syncthreads();  // rf reads done -> buf0 reusable
  }

  issue(TPT - 1, 0);  // prefetch pass-1 first tile (reverse order) during handshake
  signal_wait(0);
  combine_v(g_spart[0][0][b], g_spart[0][1][b], bias, vs, tid);
  __syncthreads();

  float vr0[N];
#pragma unroll
  for (int n = 0; n < N; ++n) vr0[n] = vs[lane * N + n];

  // ================= PASS 1: sort + mask + softmax (reverse tiles) ==========
  float sacc[N];
#pragma unroll
  for (int n = 0; n < N; ++n) sacc[n] = 0.f;
  float eu = 0.f, el = 0.f;

  for (int t = 0; t < TPT; ++t) {
    const int pt = TPT - 1 - t;
    if (t + 1 < TPT) {
      issue(TPT - 2 - t, (t + 1) & 1);
      asm volatile("cp.async.wait_group 1;\n" ::: "memory");
    } else {
      asm volatile("cp.async.wait_group 0;\n" ::: "memory");
    }
    __syncthreads();
    const float* us = (t & 1) ? buf1 : buf0;

#pragma unroll
    for (int q = 0; q < 3; ++q) {  // 3 independent i-chains per warp
      const int ii = w + q * WARPS;
      float ur[N];
      const float4* up = reinterpret_cast<const float4*>(&us[lane * ROW + ii * N]);
#pragma unroll
      for (int p = 0; p < 4; ++p) {
        float4 x = up[p];
        ur[p * 4 + 0] = x.x; ur[p * 4 + 1] = x.y;
        ur[p * 4 + 2] = x.z; ur[p * 4 + 3] = x.w;
      }
      float d0 = 0.f;
#pragma unroll
      for (int n = 0; n < N; ++n) d0 = fmaf(ur[n], vr0[n], d0);
      // bitonic sort over lanes -> kth smallest
      float xs = d0;
#pragma unroll
      for (int k = 2; k <= 32; k <<= 1) {
#pragma unroll
        for (int j = k >> 1; j > 0; j >>= 1) {
          float y = __shfl_xor_sync(FULL, xs, j);
          bool take_min = (((lane & j) == 0) == ((lane & k) == 0));
          xs = take_min ? fminf(xs, y) : fmaxf(xs, y);
        }
      }
      float kth = __shfl_sync(FULL, xs, KTH);
      bool msk = (d0 <= kth);
      unsigned bal = __ballot_sync(FULL, msk);
      if (lane == 0) maskb[pt * TI + ii] = bal;
      float e = msk ? 0.f : __expf(d0);  // no max-sub: |d0| <= ~6 (||v0||<1)
      float S = warp_sum(e);
      float cc = e / S;
      eu += __logf(S);
      el = fmaf(cc, d0, el);  // cc=0 when masked
#pragma unroll
      for (int n = 0; n < N; ++n) sacc[n] = fmaf(cc, ur[n], sacc[n]);
    }
    __syncthreads();
  }

  // pass-1 writeback (pipeline drained -> red/buf0 free)
  {
    float ent = eu - warp_sum(el);
    if (lane == 0) entw[w] = ent;
#pragma unroll
    for (int n = 0; n < N; ++n) red[w * REDSTRIDE + lane * 17 + n] = sacc[n];
    __syncthreads();
#pragma unroll
    for (int r = 0; r < 2; ++r) {
      int e = tid + r * TPB;
      int jj = e >> 4, nn = e & 15;
      float s = 0.f;
#pragma unroll
      for (int ww = 0; ww < WARPS; ++ww) s += red[ww * REDSTRIDE + jj * 17 + nn];
      __stcg(&g_spart[1][g][b][e], s);
    }
    if (tid == 0) {
      float es = 0.f;
#pragma unroll
      for (int ww = 0; ww < WARPS; ++ww) es += entw[ww];
      g_entp[0][b * NCHB + g] = es;
    }
    __syncthreads();  // red reads done -> buf0 reusable
  }

  issue(0, 0);  // prefetch pass-2 first tile (forward order)
  signal_wait(1);
  combine_v(g_spart[1][0][b], g_spart[1][1][b], bias, vs, tid);
  __syncthreads();

  float wr[N];
#pragma unroll
  for (int n = 0; n < N; ++n) wr[n] = vr0[n] + vs[lane * N + n];  // w = v0 + v1

  // ================= PASS 2: mask-propagated softmax (forward tiles) ========
#pragma unroll
  for (int n = 0; n < N; ++n) sacc[n] = 0.f;
  eu = 0.f; el = 0.f;

  for (int t = 0; t < TPT; ++t) {
    const int pt = t;
    if (t + 1 < TPT) {
      issue(t + 1, (t + 1) & 1);
      asm volatile("cp.async.wait_group 1;\n" ::: "memory");
    } else {
      asm volatile("cp.async.wait_group 0;\n" ::: "memory");
    }
    __syncthreads();
    const float* us = (t & 1) ? buf1 : buf0;

#pragma unroll
    for (int q = 0; q < 3; ++q) {
      const int ii = w + q * WARPS;
      float ur[N];
      const float4* up = reinterpret_cast<const float4*>(&us[lane * ROW + ii * N]);
#pragma unroll
      for (int p = 0; p < 4; ++p) {
        float4 x = up[p];
        ur[p * 4 + 0] = x.x; ur[p * 4 + 1] = x.y;
        ur[p * 4 + 2] = x.z; ur[p * 4 + 3] = x.w;
      }
      float d = 0.f;  // b2 (unmasked) = u . (v0+v1)
#pragma unroll
      for (int n = 0; n < N; ++n) d = fmaf(ur[n], wr[n], d);
      bool msk = (maskb[pt * TI + ii] >> lane) & 1;
      float e = msk ? 0.f : __expf(d);
      float S = warp_sum(e);
      float cc = e / S;
      eu += __logf(S);
      el = fmaf(cc, d, el);
#pragma unroll
      for (int n = 0; n < N; ++n) sacc[n] = fmaf(cc, ur[n], sacc[n]);
    }
    __syncthreads();
  }

  // pass-2 writeback
  {
    float ent = eu - warp_sum(el);
    if (lane == 0) entw[w] = ent;
#pragma unroll
    for (int n = 0; n < N; ++n) red[w * REDSTRIDE + lane * 17 + n] = sacc[n];
    __syncthreads();
#pragma unroll
    for (int r = 0; r < 2; ++r) {
      int e = tid + r * TPB;
      int jj = e >> 4, nn = e & 15;
      float s = 0.f;
#pragma unroll
      for (int ww = 0; ww < WARPS; ++ww) s += red[ww * REDSTRIDE + jj * 17 + nn];
      __stcg(&g_spart[2][g][b][e], s);
    }
    if (tid == 0) {
      float es = 0.f;
#pragma unroll
      for (int ww = 0; ww < WARPS; ++ww) es += entw[ww];
      g_entp[1][b * NCHB + g] = es;
    }
  }

  signal_wait(2);

  // final combine + squash -> out (each block writes its half of the 512)
  {
    int e = g * TPB + tid;
    float s = __ldcg(g_spart[2][0][b] + e) + __ldcg(g_spart[2][1][b] + e);
    float ssum = grp16_sum(s);
    float sb = (ssum == 0.f) ? 0.f : s + bias[e];
    float sq = grp16_sum(sb * sb);
    out[b * (J * N) + e] = (sq > 0.f) ? sb * (sq / (1.f + sq)) * rsqrtf(sq) : 0.f;
  }

  // ======== last block out: stats (fixed order -> deterministic) + reset ====
  __shared__ int s_last;
  __threadfence();
  __syncthreads();
  if (tid == 0) s_last = (atomicAdd(&g_done, 1) == NCHB * B - 1) ? 1 : 0;
  __syncthreads();
  if (s_last) {
    if (w == 0 && has_stats) {
      float a1 = 0.f, a2 = 0.f;
#pragma unroll
      for (int t = 0; t < (NCHB * B) / 32; ++t) {  // lane-strided, fixed order
        a1 += g_entp[0][lane + t * 32];
        a2 += g_entp[1][lane + t * 32];
      }
      a1 = warp_sum(a1);
      a2 = warp_sum(a2);
      if (lane == 0) {
        out[B * J * N + 0] = logf(32.0f);  // entropy of uniform softmax (iter 0)
        out[B * J * N + 1] = a1 / (float)(B * I);
        out[B * J * N + 2] = a2 / (float)(B * I);
      }
    }
    for (int t = tid; t < B * 3; t += TPB) ((int*)g_sync)[t] = 0;
    __syncthreads();
    if (tid == 0) g_done = 0;
  }
}

extern "C" void kernel_launch(void* const* d_in, const int* in_sizes, int n_in,
                              void* d_out, int out_size) {
  const float* u = (const float*)d_in[0];
  const float* bias = (const float*)d_in[1];
  float* out = (float*)d_out;
  const int has_stats = (out_size >= B * J * N + 3) ? 1 : 0;

  const size_t sh = SMEM_FLOATS * sizeof(float);  // 103.7 KB -> 2 blocks/SM
  cudaFuncSetAttribute(routing_kernel, cudaFuncAttributeMaxDynamicSharedMemorySize, (int)sh);

  routing_kernel<<<dim3(NCHB, B), TPB, sh>>>(u, bias, out, has_stats);
}

// round 15
// speedup vs baseline: 1.2157x; 1.2157x over previous
#include <cuda_runtime.h>
#include <math.h>

#define FULL 0xffffffffu

constexpr int B = 128, J = 32, I = 1152, N = 16;
constexpr int TI = 16;             // i per tile (passes 1-2)
constexpr int ROW = TI * N + 4;    // 260: conflict-free LDS.128
constexpr int NCHB = 2;            // blocks per batch
constexpr int IPB = I / NCHB;      // 576
constexpr int TPT = IPB / TI;      // 36 tiles
constexpr int TPB = 256, WARPS = 8;
constexpr int KTH = 8;             // int(0.3*32)-1
constexpr int BUF = J * ROW;       // 8320 floats
constexpr int REDSTRIDE = 544;
constexpr int SMEM_FLOATS = 2 * BUF + 512 + 8 + WARPS * REDSTRIDE + IPB;

__device__ float g_spart[3][NCHB][B][J * N];
__device__ float g_entp[2][B * NCHB];
__device__ int g_sync[B][3];
__device__ int g_done;

__device__ __forceinline__ float warp_sum(float x) {
#pragma unroll
  for (int m = 16; m; m >>= 1) x += __shfl_xor_sync(FULL, x, m);
  return x;
}
__device__ __forceinline__ float grp16_sum(float x) {
#pragma unroll
  for (int m = 8; m; m >>= 1) x += __shfl_xor_sync(FULL, x, m);
  return x;
}

// combine two chunk partials (via L2) -> s; bias + reset + squash -> v (smem)
__device__ __forceinline__ void combine_v(const float* __restrict__ p0,
                                          const float* __restrict__ p1,
                                          const float* __restrict__ bias,
                                          float* vout, int tid) {
#pragma unroll
  for (int r = 0; r < 2; ++r) {
    int e = tid + r * TPB;  // e = j*16+n, 16-groups warp-aligned
    float s = __ldcg(p0 + e) + __ldcg(p1 + e);
    float ssum = grp16_sum(s);
    float sb = (ssum == 0.f) ? 0.f : s + bias[e];
    float sq = grp16_sum(sb * sb);
    vout[e] = (sq > 0.f) ? sb * (sq / (1.f + sq)) * rsqrtf(sq) : 0.f;
  }
}

__global__ void __launch_bounds__(TPB, 2) routing_kernel(const float* __restrict__ u,
                                                         const float* __restrict__ bias,
                                                         float* __restrict__ out,
                                                         int has_stats) {
  extern __shared__ float smem[];
  float* buf0 = smem;
  float* buf1 = smem + BUF;
  float* vs = smem + 2 * BUF;  // 512
  float* entw = vs + 512;      // 8
  float* red = entw + 8;       // 4352
  unsigned* maskb = (unsigned*)(red + WARPS * REDSTRIDE);  // 576

  const int b = blockIdx.y, g = blockIdx.x;
  const int tid = threadIdx.x, w = tid >> 5, lane = tid & 31;
  const int ibase = g * IPB;

  auto issue = [&](int pt, int sel) {
    float* buf = sel ? buf1 : buf0;
#pragma unroll
    for (int k = 0; k < 8; ++k) {
      int f = tid + k * TPB;       // 2048 x 16B
      int j = f >> 6, o = f & 63;  // 64 float4 per j-row
      const float* gp = u + (((size_t)b * J + j) * I + (ibase + pt * TI)) * N + o * 4;
      unsigned sa = (unsigned)__cvta_generic_to_shared(buf + j * ROW + o * 4);
      asm volatile("cp.async.cg.shared.global [%0], [%1], 16;\n" ::"r"(sa), "l"(gp));
    }
    asm volatile("cp.async.commit_group;\n");
  };

  auto signal_wait = [&](int ph) {
    __threadfence();
    __syncthreads();
    if (tid == 0) {
      atomicAdd(&g_sync[b][ph], 1);
      while (atomicAdd(&g_sync[b][ph], 0) < 2) {}
      __threadfence();
    }
    __syncthreads();
  };

  // ================= PASS 0: direct streaming sum, c = 1/32 =================
  {
    const int half = tid >> 7, t2 = tid & 127, j0 = t2 >> 2, n4 = t2 & 3;
    const float4* p =
        (const float4*)(u + (((size_t)b * J + j0) * I + ibase + half * (IPB / 2)) * N) + n4;
    float4 a = make_float4(0.f, 0.f, 0.f, 0.f);
#pragma unroll 8
    for (int i = 0; i < IPB / 2; ++i) {
      float4 x = p[i * 4];
      a.x += x.x; a.y += x.y; a.z += x.z; a.w += x.w;
    }
    float4* rf = (float4*)red;
    rf[tid] = a;
    __syncthreads();
    if (tid < 128) {
      float4 a0 = rf[tid], a1 = rf[tid + 128];
      float4 s = make_float4((a0.x + a1.x) * (1.f / 32.f), (a0.y + a1.y) * (1.f / 32.f),
                             (a0.z + a1.z) * (1.f / 32.f), (a0.w + a1.w) * (1.f / 32.f));
      __stcg((float4*)(g_spart[0][g][b] + j0 * 16 + n4 * 4), s);
    }
  }

  issue(TPT - 1, 0);  // prefetch pass-1 first tile (reverse order) during handshake
  signal_wait(0);
  combine_v(g_spart[0][0][b], g_spart[0][1][b], bias, vs, tid);
  __syncthreads();

  float vr0[N];
#pragma unroll
  for (int n = 0; n < N; ++n) vr0[n] = vs[lane * N + n];

  // ====== PASS 1: sort + mask + softmax (reverse tiles, dual i-chains) ======
  float sacc[N];
#pragma unroll
  for (int n = 0; n < N; ++n) sacc[n] = 0.f;
  float eu = 0.f, el = 0.f;

  for (int t = 0; t < TPT; ++t) {
    const int pt = TPT - 1 - t;
    if (t + 1 < TPT) {
      issue(TPT - 2 - t, (t + 1) & 1);
      asm volatile("cp.async.wait_group 1;\n" ::: "memory");
    } else {
      asm volatile("cp.async.wait_group 0;\n" ::: "memory");
    }
    __syncthreads();
    const float* us = (t & 1) ? buf1 : buf0;

    // load both i-chains (i = w and w+8)
    float ur0[N], ur1[N];
    {
      const float4* up0 = reinterpret_cast<const float4*>(&us[lane * ROW + w * N]);
      const float4* up1 = reinterpret_cast<const float4*>(&us[lane * ROW + (w + WARPS) * N]);
#pragma unroll
      for (int p = 0; p < 4; ++p) {
        float4 x = up0[p], y = up1[p];
        ur0[p * 4 + 0] = x.x; ur0[p * 4 + 1] = x.y; ur0[p * 4 + 2] = x.z; ur0[p * 4 + 3] = x.w;
        ur1[p * 4 + 0] = y.x; ur1[p * 4 + 1] = y.y; ur1[p * 4 + 2] = y.z; ur1[p * 4 + 3] = y.w;
      }
    }
    float d0 = 0.f, d1 = 0.f;
#pragma unroll
    for (int n = 0; n < N; ++n) {
      d0 = fmaf(ur0[n], vr0[n], d0);
      d1 = fmaf(ur1[n], vr0[n], d1);
    }
    // two bitonic sorts, lock-step interleaved; lane predicate shared
    float xs0 = d0, xs1 = d1;
#pragma unroll
    for (int k = 2; k <= 32; k <<= 1) {
#pragma unroll
      for (int j = k >> 1; j > 0; j >>= 1) {
        float y0 = __shfl_xor_sync(FULL, xs0, j);
        float y1 = __shfl_xor_sync(FULL, xs1, j);
        bool take_min = (((lane & j) == 0) == ((lane & k) == 0));
        xs0 = take_min ? fminf(xs0, y0) : fmaxf(xs0, y0);
        xs1 = take_min ? fminf(xs1, y1) : fmaxf(xs1, y1);
      }
    }
    float kth0 = __shfl_sync(FULL, xs0, KTH);
    float kth1 = __shfl_sync(FULL, xs1, KTH);
    bool msk0 = (d0 <= kth0), msk1 = (d1 <= kth1);
    unsigned bal0 = __ballot_sync(FULL, msk0);
    unsigned bal1 = __ballot_sync(FULL, msk1);
    if (lane == 0) {
      maskb[pt * TI + w] = bal0;
      maskb[pt * TI + w + WARPS] = bal1;
    }
    float e0 = msk0 ? 0.f : __expf(d0);  // no max-sub: |d| <= ~6 (||v0||<1)
    float e1 = msk1 ? 0.f : __expf(d1);
    float S0 = e0, S1 = e1;
#pragma unroll
    for (int m = 16; m; m >>= 1) {  // dual warp_sum, interleaved
      S0 += __shfl_xor_sync(FULL, S0, m);
      S1 += __shfl_xor_sync(FULL, S1, m);
    }
    float cc0 = e0 / S0, cc1 = e1 / S1;
    eu += __logf(S0) + __logf(S1);
    el = fmaf(cc0, d0, el);
    el = fmaf(cc1, d1, el);  // cc = 0 when masked
#pragma unroll
    for (int n = 0; n < N; ++n) {
      sacc[n] = fmaf(cc0, ur0[n], sacc[n]);
      sacc[n] = fmaf(cc1, ur1[n], sacc[n]);
    }
    __syncthreads();
  }

  // pass-1 writeback
  {
    float ent = eu - warp_sum(el);
    if (lane == 0) entw[w] = ent;
#pragma unroll
    for (int n = 0; n < N; ++n) red[w * REDSTRIDE + lane * 17 + n] = sacc[n];
    __syncthreads();
#pragma unroll
    for (int r = 0; r < 2; ++r) {
      int e = tid + r * TPB;
      int jj = e >> 4, nn = e & 15;
      float s = 0.f;
#pragma unroll
      for (int ww = 0; ww < WARPS; ++ww) s += red[ww * REDSTRIDE + jj * 17 + nn];
      __stcg(&g_spart[1][g][b][e], s);
    }
    if (tid == 0) {
      float es = 0.f;
#pragma unroll
      for (int ww = 0; ww < WARPS; ++ww) es += entw[ww];
      g_entp[0][b * NCHB + g] = es;
    }
  }

  issue(0, 0);  // prefetch pass-2 first tile (forward order)
  signal_wait(1);
  combine_v(g_spart[1][0][b], g_spart[1][1][b], bias, vs, tid);
  __syncthreads();

  float wr[N];
#pragma unroll
  for (int n = 0; n < N; ++n) wr[n] = vr0[n] + vs[lane * N + n];  // w = v0 + v1

  // ====== PASS 2: mask-propagated softmax (forward tiles, dual i-chains) ====
#pragma unroll
  for (int n = 0; n < N; ++n) sacc[n] = 0.f;
  eu = 0.f; el = 0.f;

  for (int t = 0; t < TPT; ++t) {
    const int pt = t;
    if (t + 1 < TPT) {
      issue(t + 1, (t + 1) & 1);
      asm volatile("cp.async.wait_group 1;\n" ::: "memory");
    } else {
      asm volatile("cp.async.wait_group 0;\n" ::: "memory");
    }
    __syncthreads();
    const float* us = (t & 1) ? buf1 : buf0;

    float ur0[N], ur1[N];
    {
      const float4* up0 = reinterpret_cast<const float4*>(&us[lane * ROW + w * N]);
      const float4* up1 = reinterpret_cast<const float4*>(&us[lane * ROW + (w + WARPS) * N]);
#pragma unroll
      for (int p = 0; p < 4; ++p) {
        float4 x = up0[p], y = up1[p];
        ur0[p * 4 + 0] = x.x; ur0[p * 4 + 1] = x.y; ur0[p * 4 + 2] = x.z; ur0[p * 4 + 3] = x.w;
        ur1[p * 4 + 0] = y.x; ur1[p * 4 + 1] = y.y; ur1[p * 4 + 2] = y.z; ur1[p * 4 + 3] = y.w;
      }
    }
    float d0 = 0.f, d1 = 0.f;  // b2 (unmasked) = u . (v0+v1)
#pragma unroll
    for (int n = 0; n < N; ++n) {
      d0 = fmaf(ur0[n], wr[n], d0);
      d1 = fmaf(ur1[n], wr[n], d1);
    }
    bool msk0 = (maskb[pt * TI + w] >> lane) & 1;
    bool msk1 = (maskb[pt * TI + w + WARPS] >> lane) & 1;
    float e0 = msk0 ? 0.f : __expf(d0);
    float e1 = msk1 ? 0.f : __expf(d1);
    float S0 = e0, S1 = e1;
#pragma unroll
    for (int m = 16; m; m >>= 1) {
      S0 += __shfl_xor_sync(FULL, S0, m);
      S1 += __shfl_xor_sync(FULL, S1, m);
    }
    float cc0 = e0 / S0, cc1 = e1 / S1;
    eu += __logf(S0) + __logf(S1);
    el = fmaf(cc0, d0, el);
    el = fmaf(cc1, d1, el);
#pragma unroll
    for (int n = 0; n < N; ++n) {
      sacc[n] = fmaf(cc0, ur0[n], sacc[n]);
      sacc[n] = fmaf(cc1, ur1[n], sacc[n]);
    }
    __syncthreads();
  }

  // pass-2 writeback
  {
    float ent = eu - warp_sum(el);
    if (lane == 0) entw[w] = ent;
#pragma unroll
    for (int n = 0; n < N; ++n) red[w * REDSTRIDE + lane * 17 + n] = sacc[n];
    __syncthreads();
#pragma unroll
    for (int r = 0; r < 2; ++r) {
      int e = tid + r * TPB;
      int jj = e >> 4, nn = e & 15;
      float s = 0.f;
#pragma unroll
      for (int ww = 0; ww < WARPS; ++ww) s += red[ww * REDSTRIDE + jj * 17 + nn];
      __stcg(&g_spart[2][g][b][e], s);
    }
    if (tid == 0) {
      float es = 0.f;
#pragma unroll
      for (int ww = 0; ww < WARPS; ++ww) es += entw[ww];
      g_entp[1][b * NCHB + g] = es;
    }
  }

  signal_wait(2);

  // final combine + squash -> out (each block writes its half of the 512)
  {
    int e = g * TPB + tid;
    float s = __ldcg(g_spart[2][0][b] + e) + __ldcg(g_spart[2][1][b] + e);
    float ssum = grp16_sum(s);
    float sb = (ssum == 0.f) ? 0.f : s + bias[e];
    float sq = grp16_sum(sb * sb);
    out[b * (J * N) + e] = (sq > 0.f) ? sb * (sq / (1.f + sq)) * rsqrtf(sq) : 0.f;
  }

  // ======== last block out: stats (fixed order -> deterministic) + reset ====
  __shared__ int s_last;
  __threadfence();
  __syncthreads();
  if (tid == 0) s_last = (atomicAdd(&g_done, 1) == NCHB * B - 1) ? 1 : 0;
  __syncthreads();
  if (s_last) {
    if (w == 0 && has_stats) {
      float a1 = 0.f, a2 = 0.f;
#pragma unroll
      for (int t = 0; t < (NCHB * B) / 32; ++t) {  // lane-strided, fixed order
        a1 += g_entp[0][lane + t * 32];
        a2 += g_entp[1][lane + t * 32];
      }
      a1 = warp_sum(a1);
      a2 = warp_sum(a2);
      if (lane == 0) {
        out[B * J * N + 0] = logf(32.0f);  // entropy of uniform softmax (iter 0)
        out[B * J * N + 1] = a1 / (float)(B * I);
        out[B * J * N + 2] = a2 / (float)(B * I);
      }
    }
    for (int t = tid; t < B * 3; t += TPB) ((int*)g_sync)[t] = 0;
    __syncthreads();
    if (tid == 0) g_done = 0;
  }
}

extern "C" void kernel_launch(void* const* d_in, const int* in_sizes, int n_in,
                              void* d_out, int out_size) {
  const float* u = (const float*)d_in[0];
  const float* bias = (const float*)d_in[1];
  float* out = (float*)d_out;
  const int has_stats = (out_size >= B * J * N + 3) ? 1 : 0;

  const size_t sh = SMEM_FLOATS * sizeof(float);  // ~86.3 KB -> 2 blocks/SM
  cudaFuncSetAttribute(routing_kernel, cudaFuncAttributeMaxDynamicSharedMemorySize, (int)sh);

  routing_kernel<<<dim3(NCHB, B), TPB, sh>>>(u, bias, out, has_stats);
}